// round 13
// baseline (speedup 1.0000x reference)
#include <cuda_runtime.h>

#define BB   16
#define HH   256
#define WW   256
#define CC   32
#define EM0_ 16
#define EM1_ 17
#define NKH  32

typedef unsigned long long u64;

__device__ __forceinline__ u64 ffma2(u64 a, u64 b, u64 c) {
    u64 d;
    asm("fma.rn.f32x2 %0, %1, %2, %3;" : "=l"(d) : "l"(a), "l"(b), "l"(c));
    return d;
}
__device__ __forceinline__ float2 upk(u64 v) {
    float2 r;
    asm("mov.b64 {%0,%1}, %2;" : "=f"(r.x), "=f"(r.y) : "l"(v));
    return r;
}
__device__ __forceinline__ u64 pk(float x, float y) {
    u64 v;
    asm("mov.b64 %0, {%1,%2};" : "=l"(v) : "f"(x), "f"(y));
    return v;
}

// ---- twiddle tables (pair-packed float4 = ulonglong2 for LDS.128) ----
__device__ float4 g_tA2 [128 * 9];   // [wp][binpair]  (c0,-s0, c1,-s1)
__device__ float4 g_tB8 [16 * 128];  // [khpair][hp]   (c0,s0, c1,s1)  m signed
__device__ float4 g_tD1p[17 * 128];  // [r][hpair]     (c(h even),s, c(h odd),s)
__device__ float4 g_tD2p[129 * 9];   // [wp][kwpair]   (c0,s0, c1,s1)

// ---- scratch ----
__device__ float2 g_Xw[BB * HH * EM1_ * CC];       // after W-DFT
__device__ float4 g_Xm4[BB * NKH * EM1_ * CC];     // after H-DFT (re,re,im,im)
__device__ float4 g_SD[BB * EM1_ * EM1_ * CC];     // folded modes (S.x,-D.y,S.y,D.x)
__device__ float2 g_Z [BB * HH * EM1_ * CC];       // after inverse H-DFT
__device__ float4 g_wT2[NKH * EM1_ * CC * CC];     // ((wr,wi),(-wi,wr))

// ---------------------------------------------------------------------------
// Twiddle tables (launch 0)
__global__ void k_init() {
    int idx = blockIdx.x * 256 + threadIdx.x;
    if (idx < 1152) {                         // g_tA2
        int wp = idx / 9, bp = idx % 9;
        int b0 = 2 * bp, b1 = 2 * bp + 1;
        float s0, c0, s1 = 0.f, c1 = 0.f;
        sincospif((float)((b0 * wp) & 255) / 128.f, &s0, &c0);
        if (b1 <= 16) sincospif((float)((b1 * wp) & 255) / 128.f, &s1, &c1);
        g_tA2[idx] = make_float4(c0, -s0, c1, -s1);
    }
    int j = idx - 1152;
    if (j >= 0 && j < 2048) {                 // g_tB8
        int kp = j >> 7, hp = j & 127;
        int kh0 = 2 * kp, kh1 = 2 * kp + 1;
        int m0 = (kh0 < EM0_) ? kh0 : kh0 - NKH;
        int m1 = (kh1 < EM0_) ? kh1 : kh1 - NKH;
        float s0, c0, s1, c1;
        sincospif((float)((m0 * hp) & 255) / 128.f, &s0, &c0);
        sincospif((float)((m1 * hp) & 255) / 128.f, &s1, &c1);
        g_tB8[j] = make_float4(c0, s0, c1, s1);
    }
    int e = j - 2048;
    if (e >= 0 && e < 2176) {                 // g_tD1p
        int r = e >> 7, hpi = e & 127;
        int m = (r < 16) ? r : -16;
        int h0 = 2 * hpi, h1 = 2 * hpi + 1;
        float s0, c0, s1, c1;
        sincospif((float)((m * h0) & 255) / 128.f, &s0, &c0);
        sincospif((float)((m * h1) & 255) / 128.f, &s1, &c1);
        g_tD1p[e] = make_float4(c0, s0, c1, s1);
    }
    int f = e - 2176;
    if (f >= 0 && f < 1161) {                 // g_tD2p
        int wp = f / 9, kp = f % 9;
        int k0 = 2 * kp, k1 = 2 * kp + 1;
        float s0, c0, s1 = 0.f, c1 = 0.f;
        sincospif((float)((k0 * wp) & 255) / 128.f, &s0, &c0);
        if (k1 <= 16) sincospif((float)((k1 * wp) & 255) / 128.f, &s1, &c1);
        g_tD2p[f] = make_float4(c0, s0, c1, s1);
    }
}

// ---------------------------------------------------------------------------
// Weight transpose (launches 1 and 2, split so kA is launch index 3)
__global__ void k_wt(const float* __restrict__ w1r, const float* __restrict__ w1i,
                     const float* __restrict__ w2r, const float* __restrict__ w2i,
                     int base) {
    int idx = base + blockIdx.x * blockDim.x + threadIdx.x;
    if (idx >= NKH * EM1_ * CC * CC) return;
    int o = idx & 31;
    int t = idx >> 5;
    int i = t & 31; t >>= 5;
    int kw = t % EM1_;
    int kh = t / EM1_;
    int khm = (kh < EM0_) ? kh : kh - EM0_;
    const float* wr = (kh < EM0_) ? w1r : w2r;
    const float* wi = (kh < EM0_) ? w1i : w2i;
    int s = ((i * CC + o) * EM0_ + khm) * EM1_ + kw;
    float vr = wr[s], vi = wi[s];
    g_wT2[((kh * EM1_ + kw) * CC + i) * CC + o] = make_float4(vr, vi, -vi, vr);
}

// ---------------------------------------------------------------------------
// Stage A: folded partial real DFT along W. Block = 2 h rows, 256 threads
// = (ipair16, h2, wq8). Each thread: all 17 bins, 2 channels, 16 w'-pairs.
__global__ void __launch_bounds__(256) kA(const float* __restrict__ x) {
    extern __shared__ char smA[];
    ulonglong2* sd = (ulonglong2*)smA;              // [h][wp][ip] 64KB
    ulonglong2* tw = (ulonglong2*)(smA + 65536);    // [wp][bp]    18KB
    u64*      red = (u64*)smA;                      // reused after sync (8*1088 u64)

    int b = blockIdx.x >> 7, h0 = (blockIdx.x & 127) << 1;
    const float* xb = x + ((size_t)(b * HH + h0)) * (WW * CC);
    int tid = threadIdx.x;

    for (int t = tid; t < 128 * 9; t += 256)
        tw[t] = ((const ulonglong2*)g_tA2)[t];
    for (int p = tid; p < 2048; p += 256) {
        int wp = p >> 4, c4 = p & 15, h = c4 >> 3, ch = c4 & 7;
        int partner = wp ? (256 - wp) : 128;
        float4 a = *(const float4*)&xb[h * (WW * CC) + wp * CC + ch * 4];
        float4 e = *(const float4*)&xb[h * (WW * CC) + partner * CC + ch * 4];
        float4* dst = (float4*)sd;
        int base = (h * 128 + wp) * 16 + ch * 2;
        dst[base    ] = make_float4(a.x + e.x, a.x - e.x, a.y + e.y, a.y - e.y);
        dst[base + 1] = make_float4(a.z + e.z, a.z - e.z, a.w + e.w, a.w - e.w);
    }
    __syncthreads();

    int ip = tid & 15, h = (tid >> 4) & 1, wq = tid >> 5;  // wq 0..7
    u64 acc[18][2];
#pragma unroll
    for (int bb = 0; bb < 18; bb++) { acc[bb][0] = 0ull; acc[bb][1] = 0ull; }
    if (wq == 0) {   // w'=0 boundary: re = S for even bins, D for odd; im = 0
        ulonglong2 q0 = sd[(h * 128) * 16 + ip];
        float2 v0 = upk(q0.x), v1 = upk(q0.y);
#pragma unroll
        for (int bb = 0; bb < 17; bb++) {
            acc[bb][0] = pk((bb & 1) ? v0.y : v0.x, 0.f);
            acc[bb][1] = pk((bb & 1) ? v1.y : v1.x, 0.f);
        }
    }
    int w_lo = (wq == 0) ? 1 : wq * 16;
    int w_hi = wq * 16 + 16;
    for (int wp = w_lo; wp < w_hi; wp++) {
        ulonglong2 q = sd[(h * 128 + wp) * 16 + ip];
#pragma unroll
        for (int bp = 0; bp < 9; bp++) {
            ulonglong2 t = tw[wp * 9 + bp];
            acc[2*bp  ][0] = ffma2(q.x, t.x, acc[2*bp  ][0]);
            acc[2*bp  ][1] = ffma2(q.y, t.x, acc[2*bp  ][1]);
            acc[2*bp+1][0] = ffma2(q.x, t.y, acc[2*bp+1][0]);
            acc[2*bp+1][1] = ffma2(q.y, t.y, acc[2*bp+1][1]);
        }
    }
    __syncthreads();
#pragma unroll
    for (int bb = 0; bb < 17; bb++) {
        red[wq * 1088 + ((h * 17 + bb) * 16 + ip) * 2    ] = acc[bb][0];
        red[wq * 1088 + ((h * 17 + bb) * 16 + ip) * 2 + 1] = acc[bb][1];
    }
    __syncthreads();
    const float sc = 1.f / 65536.f;
    for (int s = tid; s < 1088; s += 256) {
        float re = 0.f, im = 0.f;
#pragma unroll
        for (int k = 0; k < 8; k++) {
            float2 a = upk(red[k * 1088 + s]);
            re += a.x; im += a.y;
        }
        int chi = s & 1, t2 = s >> 1;
        int ipp = t2 & 15, t3 = t2 >> 4;   // t3 in 0..33
        int bb = t3 % 17, hh = t3 / 17;    // hh in 0..1
        g_Xw[((size_t)(b * HH + h0 + hh) * EM1_ + bb) * CC + ipp * 2 + chi]
            = make_float2(re * sc, im * sc);
    }
}

// ---------------------------------------------------------------------------
// Stage B: folded complex DFT along H. Block=(b,kw), 256 thr = (i32, kg8 of 4 kh).
// Output written pre-duplicated (re,re,im,im) for kC's broadcast LDS.128.
__global__ void __launch_bounds__(256) kB() {
    extern __shared__ char smB[];
    ulonglong2* sdB = (ulonglong2*)smB;              // [hp-1][i] 65KB
    ulonglong2* twB = (ulonglong2*)(smB + 65024);    // [khpair][hp] 32KB
    int b = blockIdx.x / EM1_, kw = blockIdx.x % EM1_;
    int tid = threadIdx.x;
    for (int t = tid; t < 16 * 128; t += 256)
        twB[t] = ((const ulonglong2*)g_tB8)[t];
    for (int idx = tid; idx < 127 * 32; idx += 256) {
        int hp = (idx >> 5) + 1, i = idx & 31;
        float2 v  = g_Xw[((size_t)(b * HH + hp) * EM1_ + kw) * CC + i];
        float2 vp = g_Xw[((size_t)(b * HH + 256 - hp) * EM1_ + kw) * CC + i];
        ((float4*)sdB)[idx] = make_float4(v.x + vp.x, v.y - vp.y,
                                          v.y + vp.y, -(v.x - vp.x));
    }
    __syncthreads();
    int i = tid & 31, kg = tid >> 5;   // kg 0..7, 4 kh each
    float2 v0  = g_Xw[((size_t)(b * HH)       * EM1_ + kw) * CC + i];
    float2 v12 = g_Xw[((size_t)(b * HH + 128) * EM1_ + kw) * CC + i];
    u64 accA[4], accB[4];
#pragma unroll
    for (int t = 0; t < 4; t++) {
        float p = ((kg * 4 + t) & 1) ? -1.f : 1.f;
        accA[t] = pk(v0.x + p * v12.x, 0.f);
        accB[t] = pk(v0.y + p * v12.y, 0.f);
    }
#pragma unroll 4
    for (int hp = 1; hp < 128; hp++) {
        ulonglong2 q  = sdB[(hp - 1) * 32 + i];
        ulonglong2 t0 = twB[(kg * 2    ) * 128 + hp];
        ulonglong2 t1 = twB[(kg * 2 + 1) * 128 + hp];
        accA[0] = ffma2(q.x, t0.x, accA[0]); accB[0] = ffma2(q.y, t0.x, accB[0]);
        accA[1] = ffma2(q.x, t0.y, accA[1]); accB[1] = ffma2(q.y, t0.y, accB[1]);
        accA[2] = ffma2(q.x, t1.x, accA[2]); accB[2] = ffma2(q.y, t1.x, accB[2]);
        accA[3] = ffma2(q.x, t1.y, accA[3]); accB[3] = ffma2(q.y, t1.y, accB[3]);
    }
#pragma unroll
    for (int t = 0; t < 4; t++) {
        float2 ra = upk(accA[t]), rb = upk(accB[t]);
        float re = ra.x + ra.y, im = rb.x + rb.y;
        g_Xm4[((size_t)(b * NKH + kg * 4 + t) * EM1_ + kw) * CC + i]
            = make_float4(re, re, im, im);
    }
}

// ---------------------------------------------------------------------------
// Stage C: channel mixing + Hermitian kh fold. Block = (r, kw, batch-half)
// -> grid 578. Computes kh=r and kh=32-r for 8 batches, writes g_SD.
__global__ void __launch_bounds__(256) kC() {
    extern __shared__ char smC[];
    float4* xs  = (float4*)smC;            // [mode2][b8][i32] 8KB
    u64*    red = (u64*)(smC + 8192);      // [mode2][ig8][b8][o32] 32KB
    int bx = blockIdx.x;
    int r = bx / 34;
    int rem = bx % 34;
    int kw = rem >> 1, bh = rem & 1;
    int kh2 = (r == 0 || r == 16) ? r : 32 - r;
    int tid = threadIdx.x;
    for (int t = tid; t < 512; t += 256) {
        int m = t >> 8, b = (t >> 5) & 7, i = t & 31;
        int kh = m ? kh2 : r;
        xs[t] = g_Xm4[((size_t)((bh * 8 + b) * NKH + kh) * EM1_ + kw) * CC + i];
    }
    int o = tid & 31, ig = tid >> 5;       // ig 0..7, 4 i each
    ulonglong2 wv[2][4];
#pragma unroll
    for (int m = 0; m < 2; m++) {
        int kh = m ? kh2 : r;
        const ulonglong2* wp = (const ulonglong2*)g_wT2
            + ((size_t)(kh * EM1_ + kw) * CC + ig * 4) * CC + o;
#pragma unroll
        for (int ii = 0; ii < 4; ii++) wv[m][ii] = __ldg(&wp[ii * 32]);
    }
    __syncthreads();
    u64 acc[2][8];
#pragma unroll
    for (int m = 0; m < 2; m++)
#pragma unroll
        for (int b = 0; b < 8; b++) acc[m][b] = 0ull;
#pragma unroll
    for (int ii = 0; ii < 4; ii++) {
#pragma unroll
        for (int m = 0; m < 2; m++) {
            const ulonglong2* xq = (const ulonglong2*)xs + m * 256 + ig * 4 + ii;
#pragma unroll
            for (int b = 0; b < 8; b++) {
                ulonglong2 q = xq[b * 32];     // broadcast LDS.128
                acc[m][b] = ffma2(q.x, wv[m][ii].x, acc[m][b]);
                acc[m][b] = ffma2(q.y, wv[m][ii].y, acc[m][b]);
            }
        }
    }
#pragma unroll
    for (int m = 0; m < 2; m++)
#pragma unroll
        for (int b = 0; b < 8; b++)
            red[(m * 8 + ig) * 256 + b * 32 + o] = acc[m][b];
    __syncthreads();
    float f = (kw == 0) ? 1.f : 2.f;
    {
        int t = tid;               // exactly 256 outputs
        float reA = 0.f, imA = 0.f, reB = 0.f, imB = 0.f;
#pragma unroll
        for (int g = 0; g < 8; g++) {
            float2 a  = upk(red[g * 256 + t]);
            float2 bq = upk(red[(8 + g) * 256 + t]);
            reA += a.x;  imA += a.y;
            reB += bq.x; imB += bq.y;
        }
        reA *= f; imA *= f; reB *= f; imB *= f;
        float Sx, Sy, Dx, Dy;
        if (r == 0 || r == 16) { Sx = reA; Sy = imA; Dx = reA; Dy = imA; }
        else { Sx = reA + reB; Sy = imA + imB; Dx = reA - reB; Dy = imA - imB; }
        int b = t >> 5, o2 = t & 31;
        g_SD[(size_t)((bh * 8 + b) * EM1_ + r) * 544 + kw * 32 + o2]
            = make_float4(Sx, -Dy, Sy, Dx);
    }
}

// ---------------------------------------------------------------------------
// kD1: inverse H-DFT (17 folded rows -> 8 h rows per block) -> g_Z.
// Twiddle slice staged in smem; r loop unrolled 2x for load MLP.
__global__ void __launch_bounds__(544) kD1() {
    __shared__ ulonglong2 tds[17 * 4];     // 2.2KB slice for this block's 8 rows
    int b = blockIdx.x >> 5, h0 = (blockIdx.x & 31) << 3;
    int tid = threadIdx.x;
    for (int t = tid; t < 68; t += 544) {
        int r = t >> 2, jp = t & 3;
        tds[t] = __ldg((const ulonglong2*)g_tD1p + r * 128 + (h0 >> 1) + jp);
    }
    __syncthreads();
    u64 aA[8], aB[8];
#pragma unroll
    for (int hh = 0; hh < 8; hh++) { aA[hh] = 0ull; aB[hh] = 0ull; }
    const ulonglong2* SDp = (const ulonglong2*)g_SD + (size_t)b * EM1_ * 544 + tid;
#pragma unroll 2
    for (int r = 0; r < 17; r++) {
        ulonglong2 q = SDp[r * 544];
#pragma unroll
        for (int jp = 0; jp < 4; jp++) {
            ulonglong2 t = tds[r * 4 + jp];
            aA[2*jp  ] = ffma2(q.x, t.x, aA[2*jp  ]);
            aB[2*jp  ] = ffma2(q.y, t.x, aB[2*jp  ]);
            aA[2*jp+1] = ffma2(q.x, t.y, aA[2*jp+1]);
            aB[2*jp+1] = ffma2(q.y, t.y, aB[2*jp+1]);
        }
    }
#pragma unroll
    for (int hh = 0; hh < 8; hh++) {
        float2 ra = upk(aA[hh]), rb = upk(aB[hh]);
        g_Z[(size_t)(b * HH + h0 + hh) * 544 + tid]
            = make_float2(ra.x + ra.y, rb.x + rb.y);
    }
}

// ---------------------------------------------------------------------------
// kD2: inverse real W-DFT + bias. Block = 1 h row, 256 thr = (o32, ws8).
// z[17] in registers; twiddles in smem.
__global__ void __launch_bounds__(256) kD2(const float* __restrict__ bias,
                                           float* __restrict__ y) {
    extern __shared__ char smD[];
    ulonglong2* t2s = (ulonglong2*)smD;    // [wp][kwpair] 18.6KB
    int b = blockIdx.x >> 8, h = blockIdx.x & 255;
    int tid = threadIdx.x;
    int o = tid & 31, ws = tid >> 5;
    for (int t = tid; t < 129 * 9; t += 256)
        t2s[t] = ((const ulonglong2*)g_tD2p)[t];
    float bo = __ldg(&bias[o]);
    u64 z[17];
    const u64* zp = (const u64*)g_Z + (size_t)(b * HH + h) * 544 + o;
#pragma unroll
    for (int kw = 0; kw < 17; kw++) z[kw] = __ldg(&zp[kw * 32]);
    __syncthreads();
    float* yp = y + (size_t)(b * HH + h) * WW * CC;
    int niter = (ws == 0) ? 17 : 16;
    for (int j = 0; j < niter; j++) {
        int wp = (j == 16) ? 128 : ws * 16 + j;
        u64 c0 = 0ull;
#pragma unroll
        for (int kp = 0; kp < 8; kp++) {
            ulonglong2 t = t2s[wp * 9 + kp];
            c0 = ffma2(z[2*kp], t.x, c0);
            c0 = ffma2(z[2*kp+1], t.y, c0);
        }
        {
            ulonglong2 t = t2s[wp * 9 + 8];
            c0 = ffma2(z[16], t.x, c0);
        }
        float2 f0 = upk(c0);
        yp[wp * CC + o] = bo + f0.x - f0.y;
        if (wp > 0 && wp < 128)
            yp[(256 - wp) * CC + o] = bo + f0.x + f0.y;
    }
}

// ---------------------------------------------------------------------------
extern "C" void kernel_launch(void* const* d_in, const int* in_sizes, int n_in,
                              void* d_out, int out_size) {
    const float* x    = (const float*)d_in[0];
    const float* w1r  = (const float*)d_in[1];
    const float* w1i  = (const float*)d_in[2];
    const float* w2r  = (const float*)d_in[3];
    const float* w2i  = (const float*)d_in[4];
    const float* bias = (const float*)d_in[5];
    float* y = (float*)d_out;

    cudaFuncSetAttribute(kA, cudaFuncAttributeMaxDynamicSharedMemorySize, 83968);
    cudaFuncSetAttribute(kB, cudaFuncAttributeMaxDynamicSharedMemorySize, 97792);
    cudaFuncSetAttribute(kC, cudaFuncAttributeMaxDynamicSharedMemorySize, 40960);

    // launches 0..2: setup (kA deliberately placed at launch index 3 for ncu)
    k_init<<<26, 256>>>();
    k_wt<<<1088, 256>>>(w1r, w1i, w2r, w2i, 0);
    k_wt<<<1088, 256>>>(w1r, w1i, w2r, w2i, 278528);
    kA <<<BB * HH / 2, 256, 83968>>>(x);
    kB <<<BB * EM1_, 256, 97792>>>();
    kC <<<17 * 34, 256, 40960>>>();
    kD1<<<BB * HH / 8, 544>>>();
    kD2<<<BB * HH, 256, 18576>>>(bias, y);
}

// round 15
// speedup vs baseline: 1.0179x; 1.0179x over previous
#include <cuda_runtime.h>

#define BB   16
#define HH   256
#define WW   256
#define CC   32
#define EM0_ 16
#define EM1_ 17
#define NKH  32

typedef unsigned long long u64;

__device__ __forceinline__ u64 ffma2(u64 a, u64 b, u64 c) {
    u64 d;
    asm("fma.rn.f32x2 %0, %1, %2, %3;" : "=l"(d) : "l"(a), "l"(b), "l"(c));
    return d;
}
__device__ __forceinline__ float2 upk(u64 v) {
    float2 r;
    asm("mov.b64 {%0,%1}, %2;" : "=f"(r.x), "=f"(r.y) : "l"(v));
    return r;
}
__device__ __forceinline__ u64 pk(float x, float y) {
    u64 v;
    asm("mov.b64 %0, {%1,%2};" : "=l"(v) : "f"(x), "f"(y));
    return v;
}

// ---- twiddle tables (pair-packed float4 = ulonglong2 for LDS.128) ----
__device__ float4 g_tA2 [128 * 9];   // [wp][binpair]  (c0,-s0, c1,-s1)
__device__ float4 g_tB8 [16 * 128];  // [khpair][hp]   (c0,s0, c1,s1)  m signed
__device__ float4 g_tD1p[17 * 128];  // [r][hpair]     (c(h even),s, c(h odd),s)
__device__ float4 g_tD2p[129 * 9];   // [wp][kwpair]   (c0,s0, c1,s1)

// ---- scratch ----
__device__ float2 g_Xw[BB * HH * EM1_ * CC];       // after W-DFT
__device__ float4 g_Xm4[BB * NKH * EM1_ * CC];     // after H-DFT (re,re,im,im)
__device__ float4 g_SD[BB * EM1_ * EM1_ * CC];     // folded modes (S.x,-D.y,S.y,D.x)
__device__ float2 g_Z [BB * HH * EM1_ * CC];       // after inverse H-DFT
__device__ float4 g_wT2[NKH * EM1_ * CC * CC];     // ((wr,wi),(-wi,wr))

// ---------------------------------------------------------------------------
// Twiddle tables (launch 0)
__global__ void k_init() {
    int idx = blockIdx.x * 256 + threadIdx.x;
    if (idx < 1152) {                         // g_tA2
        int wp = idx / 9, bp = idx % 9;
        int b0 = 2 * bp, b1 = 2 * bp + 1;
        float s0, c0, s1 = 0.f, c1 = 0.f;
        sincospif((float)((b0 * wp) & 255) / 128.f, &s0, &c0);
        if (b1 <= 16) sincospif((float)((b1 * wp) & 255) / 128.f, &s1, &c1);
        g_tA2[idx] = make_float4(c0, -s0, c1, -s1);
    }
    int j = idx - 1152;
    if (j >= 0 && j < 2048) {                 // g_tB8
        int kp = j >> 7, hp = j & 127;
        int kh0 = 2 * kp, kh1 = 2 * kp + 1;
        int m0 = (kh0 < EM0_) ? kh0 : kh0 - NKH;
        int m1 = (kh1 < EM0_) ? kh1 : kh1 - NKH;
        float s0, c0, s1, c1;
        sincospif((float)((m0 * hp) & 255) / 128.f, &s0, &c0);
        sincospif((float)((m1 * hp) & 255) / 128.f, &s1, &c1);
        g_tB8[j] = make_float4(c0, s0, c1, s1);
    }
    int e = j - 2048;
    if (e >= 0 && e < 2176) {                 // g_tD1p
        int r = e >> 7, hpi = e & 127;
        int m = (r < 16) ? r : -16;
        int h0 = 2 * hpi, h1 = 2 * hpi + 1;
        float s0, c0, s1, c1;
        sincospif((float)((m * h0) & 255) / 128.f, &s0, &c0);
        sincospif((float)((m * h1) & 255) / 128.f, &s1, &c1);
        g_tD1p[e] = make_float4(c0, s0, c1, s1);
    }
    int f = e - 2176;
    if (f >= 0 && f < 1161) {                 // g_tD2p
        int wp = f / 9, kp = f % 9;
        int k0 = 2 * kp, k1 = 2 * kp + 1;
        float s0, c0, s1 = 0.f, c1 = 0.f;
        sincospif((float)((k0 * wp) & 255) / 128.f, &s0, &c0);
        if (k1 <= 16) sincospif((float)((k1 * wp) & 255) / 128.f, &s1, &c1);
        g_tD2p[f] = make_float4(c0, s0, c1, s1);
    }
}

// ---------------------------------------------------------------------------
// Weight transpose (launches 1 and 2, split so kA is launch index 3)
__global__ void k_wt(const float* __restrict__ w1r, const float* __restrict__ w1i,
                     const float* __restrict__ w2r, const float* __restrict__ w2i,
                     int base) {
    int idx = base + blockIdx.x * blockDim.x + threadIdx.x;
    if (idx >= NKH * EM1_ * CC * CC) return;
    int o = idx & 31;
    int t = idx >> 5;
    int i = t & 31; t >>= 5;
    int kw = t % EM1_;
    int kh = t / EM1_;
    int khm = (kh < EM0_) ? kh : kh - EM0_;
    const float* wr = (kh < EM0_) ? w1r : w2r;
    const float* wi = (kh < EM0_) ? w1i : w2i;
    int s = ((i * CC + o) * EM0_ + khm) * EM1_ + kw;
    float vr = wr[s], vi = wi[s];
    g_wT2[((kh * EM1_ + kw) * CC + i) * CC + o] = make_float4(vr, vi, -vi, vr);
}

// ---------------------------------------------------------------------------
// Stage A: folded partial real DFT along W. Block = 2 h rows, 256 threads
// = (ipair16, h2, wq4, bg2). bg0 owns bins 0-9, bg1 bins 10-16; each thread
// covers a 32-wp slice. Twiddle table stores wp 0..64 only; upper wp derived
// by mirror symmetry T(b,128-wp) with 2 sign-XORs per bin pair.
__global__ void __launch_bounds__(256, 3) kA(const float* __restrict__ x) {
    extern __shared__ char smA[];
    ulonglong2* sd  = (ulonglong2*)smA;             // [h2][wp128][ip16] 64KB
    ulonglong2* twS = (ulonglong2*)(smA + 65536);   // [wp 0..64][bp9] 9360B
    u64*       red  = (u64*)smA;                    // post-sync: 4*1088 u64

    int b = blockIdx.x >> 7, h0 = (blockIdx.x & 127) << 1;
    const float* xb = x + ((size_t)(b * HH + h0)) * (WW * CC);
    int tid = threadIdx.x;

    for (int t = tid; t < 585; t += 256)            // wp<=64 prefix of g_tA2
        twS[t] = ((const ulonglong2*)g_tA2)[t];
    for (int p = tid; p < 2048; p += 256) {
        int wp = p >> 4, c4 = p & 15, h = c4 >> 3, ch = c4 & 7;
        int partner = wp ? (256 - wp) : 128;
        float4 a = *(const float4*)&xb[h * (WW * CC) + wp * CC + ch * 4];
        float4 e = *(const float4*)&xb[h * (WW * CC) + partner * CC + ch * 4];
        float4* dst = (float4*)sd;
        int base = (h * 128 + wp) * 16 + ch * 2;
        dst[base    ] = make_float4(a.x + e.x, a.x - e.x, a.y + e.y, a.y - e.y);
        dst[base + 1] = make_float4(a.z + e.z, a.z - e.z, a.w + e.w, a.w - e.w);
    }
    __syncthreads();

    int ip = tid & 15, h = (tid >> 4) & 1;
    int sub = tid >> 5, wq = sub & 3, bg = sub >> 2;
    int bp0 = bg ? 5 : 0;
    int nbp = bg ? 4 : 5;

    u64 acc[5][2][2];
#pragma unroll
    for (int j = 0; j < 5; j++)
#pragma unroll
        for (int k = 0; k < 2; k++) { acc[j][k][0] = 0ull; acc[j][k][1] = 0ull; }

    if (wq == 0) {   // w'=0 boundary: re = S for even bins, D for odd; im = 0
        ulonglong2 q0 = sd[(h * 128) * 16 + ip];
        float2 v0 = upk(q0.x), v1 = upk(q0.y);
#pragma unroll
        for (int j = 0; j < 5; j++) {
            if (j < nbp) {
                acc[j][0][0] = pk(v0.x, 0.f);  acc[j][0][1] = pk(v1.x, 0.f);
                acc[j][1][0] = pk(v0.y, 0.f);  acc[j][1][1] = pk(v1.y, 0.f);
            }
        }
    }

    if (wq < 2) {
        int w_lo = (wq == 0) ? 1 : 32;
        int w_hi = wq * 32 + 32;
        for (int wp = w_lo; wp < w_hi; wp++) {
            ulonglong2 q = sd[(h * 128 + wp) * 16 + ip];
#pragma unroll
            for (int j = 0; j < 5; j++) {
                if (j < nbp) {
                    ulonglong2 t = twS[wp * 9 + bp0 + j];
                    acc[j][0][0] = ffma2(q.x, t.x, acc[j][0][0]);
                    acc[j][0][1] = ffma2(q.y, t.x, acc[j][0][1]);
                    acc[j][1][0] = ffma2(q.x, t.y, acc[j][1][0]);
                    acc[j][1][1] = ffma2(q.y, t.y, acc[j][1][1]);
                }
            }
        }
    } else {
        int w_lo = wq * 32, w_hi = w_lo + 32;
        for (int wp = w_lo; wp < w_hi; wp++) {
            ulonglong2 q = sd[(h * 128 + wp) * 16 + ip];
            int wpm = 128 - wp;   // 64..33 / 32..1
#pragma unroll
            for (int j = 0; j < 5; j++) {
                if (j < nbp) {
                    ulonglong2 tr = twS[wpm * 9 + bp0 + j];
                    u64 tx = tr.x ^ 0x8000000000000000ULL;  // even bin: -s -> s
                    u64 ty = tr.y ^ 0x0000000080000000ULL;  // odd bin:  c -> -c
                    acc[j][0][0] = ffma2(q.x, tx, acc[j][0][0]);
                    acc[j][0][1] = ffma2(q.y, tx, acc[j][0][1]);
                    acc[j][1][0] = ffma2(q.x, ty, acc[j][1][0]);
                    acc[j][1][1] = ffma2(q.y, ty, acc[j][1][1]);
                }
            }
        }
    }
    __syncthreads();
#pragma unroll
    for (int j = 0; j < 5; j++) {
        if (j < nbp) {
#pragma unroll
            for (int k = 0; k < 2; k++) {
                int bb = 2 * (bp0 + j) + k;
                if (bb < 17) {
                    red[wq * 1088 + ((h * 17 + bb) * 16 + ip) * 2    ] = acc[j][k][0];
                    red[wq * 1088 + ((h * 17 + bb) * 16 + ip) * 2 + 1] = acc[j][k][1];
                }
            }
        }
    }
    __syncthreads();
    const float sc = 1.f / 65536.f;
    for (int s = tid; s < 1088; s += 256) {
        float re = 0.f, im = 0.f;
#pragma unroll
        for (int k = 0; k < 4; k++) {
            float2 a = upk(red[k * 1088 + s]);
            re += a.x; im += a.y;
        }
        int chi = s & 1, t2 = s >> 1;
        int ipp = t2 & 15, t3 = t2 >> 4;   // t3 in 0..33
        int bb = t3 % 17, hh = t3 / 17;    // hh in 0..1
        g_Xw[((size_t)(b * HH + h0 + hh) * EM1_ + bb) * CC + ipp * 2 + chi]
            = make_float2(re * sc, im * sc);
    }
}

// ---------------------------------------------------------------------------
// Stage B: folded complex DFT along H. Block=(b,kw), 256 thr = (i32, kg8 of 4 kh).
// Output written pre-duplicated (re,re,im,im) for kC's broadcast LDS.128.
__global__ void __launch_bounds__(256) kB() {
    extern __shared__ char smB[];
    ulonglong2* sdB = (ulonglong2*)smB;              // [hp-1][i] 65KB
    ulonglong2* twB = (ulonglong2*)(smB + 65024);    // [khpair][hp] 32KB
    int b = blockIdx.x / EM1_, kw = blockIdx.x % EM1_;
    int tid = threadIdx.x;
    for (int t = tid; t < 16 * 128; t += 256)
        twB[t] = ((const ulonglong2*)g_tB8)[t];
    for (int idx = tid; idx < 127 * 32; idx += 256) {
        int hp = (idx >> 5) + 1, i = idx & 31;
        float2 v  = g_Xw[((size_t)(b * HH + hp) * EM1_ + kw) * CC + i];
        float2 vp = g_Xw[((size_t)(b * HH + 256 - hp) * EM1_ + kw) * CC + i];
        ((float4*)sdB)[idx] = make_float4(v.x + vp.x, v.y - vp.y,
                                          v.y + vp.y, -(v.x - vp.x));
    }
    __syncthreads();
    int i = tid & 31, kg = tid >> 5;   // kg 0..7, 4 kh each
    float2 v0  = g_Xw[((size_t)(b * HH)       * EM1_ + kw) * CC + i];
    float2 v12 = g_Xw[((size_t)(b * HH + 128) * EM1_ + kw) * CC + i];
    u64 accA[4], accB[4];
#pragma unroll
    for (int t = 0; t < 4; t++) {
        float p = ((kg * 4 + t) & 1) ? -1.f : 1.f;
        accA[t] = pk(v0.x + p * v12.x, 0.f);
        accB[t] = pk(v0.y + p * v12.y, 0.f);
    }
#pragma unroll 4
    for (int hp = 1; hp < 128; hp++) {
        ulonglong2 q  = sdB[(hp - 1) * 32 + i];
        ulonglong2 t0 = twB[(kg * 2    ) * 128 + hp];
        ulonglong2 t1 = twB[(kg * 2 + 1) * 128 + hp];
        accA[0] = ffma2(q.x, t0.x, accA[0]); accB[0] = ffma2(q.y, t0.x, accB[0]);
        accA[1] = ffma2(q.x, t0.y, accA[1]); accB[1] = ffma2(q.y, t0.y, accB[1]);
        accA[2] = ffma2(q.x, t1.x, accA[2]); accB[2] = ffma2(q.y, t1.x, accB[2]);
        accA[3] = ffma2(q.x, t1.y, accA[3]); accB[3] = ffma2(q.y, t1.y, accB[3]);
    }
#pragma unroll
    for (int t = 0; t < 4; t++) {
        float2 ra = upk(accA[t]), rb = upk(accB[t]);
        float re = ra.x + ra.y, im = rb.x + rb.y;
        g_Xm4[((size_t)(b * NKH + kg * 4 + t) * EM1_ + kw) * CC + i]
            = make_float4(re, re, im, im);
    }
}

// ---------------------------------------------------------------------------
// Stage C: channel mixing + Hermitian kh fold. Block = (r, kw, batch-half)
// -> grid 578. Computes kh=r and kh=32-r for 8 batches, writes g_SD.
__global__ void __launch_bounds__(256) kC() {
    extern __shared__ char smC[];
    float4* xs  = (float4*)smC;            // [mode2][b8][i32] 8KB
    u64*    red = (u64*)(smC + 8192);      // [mode2][ig8][b8][o32] 32KB
    int bx = blockIdx.x;
    int r = bx / 34;
    int rem = bx % 34;
    int kw = rem >> 1, bh = rem & 1;
    int kh2 = (r == 0 || r == 16) ? r : 32 - r;
    int tid = threadIdx.x;
    for (int t = tid; t < 512; t += 256) {
        int m = t >> 8, b = (t >> 5) & 7, i = t & 31;
        int kh = m ? kh2 : r;
        xs[t] = g_Xm4[((size_t)((bh * 8 + b) * NKH + kh) * EM1_ + kw) * CC + i];
    }
    int o = tid & 31, ig = tid >> 5;       // ig 0..7, 4 i each
    ulonglong2 wv[2][4];
#pragma unroll
    for (int m = 0; m < 2; m++) {
        int kh = m ? kh2 : r;
        const ulonglong2* wp = (const ulonglong2*)g_wT2
            + ((size_t)(kh * EM1_ + kw) * CC + ig * 4) * CC + o;
#pragma unroll
        for (int ii = 0; ii < 4; ii++) wv[m][ii] = __ldg(&wp[ii * 32]);
    }
    __syncthreads();
    u64 acc[2][8];
#pragma unroll
    for (int m = 0; m < 2; m++)
#pragma unroll
        for (int b = 0; b < 8; b++) acc[m][b] = 0ull;
#pragma unroll
    for (int ii = 0; ii < 4; ii++) {
#pragma unroll
        for (int m = 0; m < 2; m++) {
            const ulonglong2* xq = (const ulonglong2*)xs + m * 256 + ig * 4 + ii;
#pragma unroll
            for (int b = 0; b < 8; b++) {
                ulonglong2 q = xq[b * 32];     // broadcast LDS.128
                acc[m][b] = ffma2(q.x, wv[m][ii].x, acc[m][b]);
                acc[m][b] = ffma2(q.y, wv[m][ii].y, acc[m][b]);
            }
        }
    }
#pragma unroll
    for (int m = 0; m < 2; m++)
#pragma unroll
        for (int b = 0; b < 8; b++)
            red[(m * 8 + ig) * 256 + b * 32 + o] = acc[m][b];
    __syncthreads();
    float f = (kw == 0) ? 1.f : 2.f;
    {
        int t = tid;               // exactly 256 outputs
        float reA = 0.f, imA = 0.f, reB = 0.f, imB = 0.f;
#pragma unroll
        for (int g = 0; g < 8; g++) {
            float2 a  = upk(red[g * 256 + t]);
            float2 bq = upk(red[(8 + g) * 256 + t]);
            reA += a.x;  imA += a.y;
            reB += bq.x; imB += bq.y;
        }
        reA *= f; imA *= f; reB *= f; imB *= f;
        float Sx, Sy, Dx, Dy;
        if (r == 0 || r == 16) { Sx = reA; Sy = imA; Dx = reA; Dy = imA; }
        else { Sx = reA + reB; Sy = imA + imB; Dx = reA - reB; Dy = imA - imB; }
        int b = t >> 5, o2 = t & 31;
        g_SD[(size_t)((bh * 8 + b) * EM1_ + r) * 544 + kw * 32 + o2]
            = make_float4(Sx, -Dy, Sy, Dx);
    }
}

// ---------------------------------------------------------------------------
// kD1: inverse H-DFT (17 folded rows -> 8 h rows per block) -> g_Z.
// Twiddle slice staged in smem; r loop unrolled 2x for load MLP.
__global__ void __launch_bounds__(544) kD1() {
    __shared__ ulonglong2 tds[17 * 4];     // 2.2KB slice for this block's 8 rows
    int b = blockIdx.x >> 5, h0 = (blockIdx.x & 31) << 3;
    int tid = threadIdx.x;
    for (int t = tid; t < 68; t += 544) {
        int r = t >> 2, jp = t & 3;
        tds[t] = __ldg((const ulonglong2*)g_tD1p + r * 128 + (h0 >> 1) + jp);
    }
    __syncthreads();
    u64 aA[8], aB[8];
#pragma unroll
    for (int hh = 0; hh < 8; hh++) { aA[hh] = 0ull; aB[hh] = 0ull; }
    const ulonglong2* SDp = (const ulonglong2*)g_SD + (size_t)b * EM1_ * 544 + tid;
#pragma unroll 2
    for (int r = 0; r < 17; r++) {
        ulonglong2 q = SDp[r * 544];
#pragma unroll
        for (int jp = 0; jp < 4; jp++) {
            ulonglong2 t = tds[r * 4 + jp];
            aA[2*jp  ] = ffma2(q.x, t.x, aA[2*jp  ]);
            aB[2*jp  ] = ffma2(q.y, t.x, aB[2*jp  ]);
            aA[2*jp+1] = ffma2(q.x, t.y, aA[2*jp+1]);
            aB[2*jp+1] = ffma2(q.y, t.y, aB[2*jp+1]);
        }
    }
#pragma unroll
    for (int hh = 0; hh < 8; hh++) {
        float2 ra = upk(aA[hh]), rb = upk(aB[hh]);
        g_Z[(size_t)(b * HH + h0 + hh) * 544 + tid]
            = make_float2(ra.x + ra.y, rb.x + rb.y);
    }
}

// ---------------------------------------------------------------------------
// kD2: inverse real W-DFT + bias. Block = 1 h row, 256 thr = (o32, ws8).
// z[17] in registers; twiddles in smem.
__global__ void __launch_bounds__(256) kD2(const float* __restrict__ bias,
                                           float* __restrict__ y) {
    extern __shared__ char smD[];
    ulonglong2* t2s = (ulonglong2*)smD;    // [wp][kwpair] 18.6KB
    int b = blockIdx.x >> 8, h = blockIdx.x & 255;
    int tid = threadIdx.x;
    int o = tid & 31, ws = tid >> 5;
    for (int t = tid; t < 129 * 9; t += 256)
        t2s[t] = ((const ulonglong2*)g_tD2p)[t];
    float bo = __ldg(&bias[o]);
    u64 z[17];
    const u64* zp = (const u64*)g_Z + (size_t)(b * HH + h) * 544 + o;
#pragma unroll
    for (int kw = 0; kw < 17; kw++) z[kw] = __ldg(&zp[kw * 32]);
    __syncthreads();
    float* yp = y + (size_t)(b * HH + h) * WW * CC;
    int niter = (ws == 0) ? 17 : 16;
    for (int j = 0; j < niter; j++) {
        int wp = (j == 16) ? 128 : ws * 16 + j;
        u64 c0 = 0ull;
#pragma unroll
        for (int kp = 0; kp < 8; kp++) {
            ulonglong2 t = t2s[wp * 9 + kp];
            c0 = ffma2(z[2*kp], t.x, c0);
            c0 = ffma2(z[2*kp+1], t.y, c0);
        }
        {
            ulonglong2 t = t2s[wp * 9 + 8];
            c0 = ffma2(z[16], t.x, c0);
        }
        float2 f0 = upk(c0);
        yp[wp * CC + o] = bo + f0.x - f0.y;
        if (wp > 0 && wp < 128)
            yp[(256 - wp) * CC + o] = bo + f0.x + f0.y;
    }
}

// ---------------------------------------------------------------------------
extern "C" void kernel_launch(void* const* d_in, const int* in_sizes, int n_in,
                              void* d_out, int out_size) {
    const float* x    = (const float*)d_in[0];
    const float* w1r  = (const float*)d_in[1];
    const float* w1i  = (const float*)d_in[2];
    const float* w2r  = (const float*)d_in[3];
    const float* w2i  = (const float*)d_in[4];
    const float* bias = (const float*)d_in[5];
    float* y = (float*)d_out;

    cudaFuncSetAttribute(kA, cudaFuncAttributeMaxDynamicSharedMemorySize, 74896);
    cudaFuncSetAttribute(kB, cudaFuncAttributeMaxDynamicSharedMemorySize, 97792);
    cudaFuncSetAttribute(kC, cudaFuncAttributeMaxDynamicSharedMemorySize, 40960);

    // launches 0..2: setup (kA deliberately placed at launch index 3 for ncu)
    k_init<<<26, 256>>>();
    k_wt<<<1088, 256>>>(w1r, w1i, w2r, w2i, 0);
    k_wt<<<1088, 256>>>(w1r, w1i, w2r, w2i, 278528);
    kA <<<BB * HH / 2, 256, 74896>>>(x);
    kB <<<BB * EM1_, 256, 97792>>>();
    kC <<<17 * 34, 256, 40960>>>();
    kD1<<<BB * HH / 8, 544>>>();
    kD2<<<BB * HH, 256, 18576>>>(bias, y);
}